// round 1
// baseline (speedup 1.0000x reference)
#include <cuda_runtime.h>
#include <cuda_bf16.h>
#include <cstdint>

// Problem-shape scratch (fixed: N=4096, D=512). __device__ globals per harness rules.
#define MAXN 4096
#define MAXD 512

__device__ float g_Kbar[MAXD * MAXD];
__device__ float g_M[MAXD * MAXD];
__device__ float g_c[MAXD];
__device__ float g_P[MAXN * MAXD];
__device__ float g_deg[MAXN];

// ---------------------------------------------------------------------------
// Kbar = mean over heads of K[h]
// ---------------------------------------------------------------------------
__global__ void kbar_kernel(const float* __restrict__ K, int H, int DD) {
    int i = blockIdx.x * blockDim.x + threadIdx.x;
    if (i < DD) {
        float s = 0.f;
        for (int h = 0; h < H; h++) s += K[(size_t)h * DD + i];
        g_Kbar[i] = s / (float)H;
    }
}

// ---------------------------------------------------------------------------
// c[f] = sum_d b[d] * Kbar[d*D+f]
// ---------------------------------------------------------------------------
__global__ void cvec_kernel(const float* __restrict__ b, int D) {
    int f = blockIdx.x * blockDim.x + threadIdx.x;
    if (f < D) {
        float s = 0.f;
        for (int d = 0; d < D; d++) s += b[d] * g_Kbar[(size_t)d * D + f];
        g_c[f] = s;
    }
}

// ---------------------------------------------------------------------------
// Sparse aggregation: P[i,:] = sum_{j: adj[i,j]>0.5} nodes[j,:]; deg[i] = count.
// One block per row, 256 threads (8 warps). Deterministic ordering:
// warp w scans columns [w*512, (w+1)*512) in order, ballot+popc compaction.
// D == 512: each thread owns columns tid and tid+256.
// ---------------------------------------------------------------------------
__global__ void agg_kernel(const float* __restrict__ adj,
                           const float* __restrict__ nodes,
                           int n, int d) {
    __shared__ int s_idx[4096];
    __shared__ int s_cnt[8];
    const int row  = blockIdx.x;
    const int tid  = threadIdx.x;
    const int w    = tid >> 5;
    const int lane = tid & 31;

    const float* arow = adj + (size_t)row * n;
    const int seg = n >> 3;          // 512 columns per warp
    const int base = w * seg;

    int cnt = 0;
    for (int s = 0; s < seg; s += 32) {
        int col = base + s + lane;
        float v = arow[col];
        unsigned m = __ballot_sync(0xffffffffu, v > 0.5f);
        if (v > 0.5f) {
            int pos = cnt + __popc(m & ((1u << lane) - 1u));
            s_idx[base + pos] = col;
        }
        cnt += __popc(m);
    }
    if (lane == 0) s_cnt[w] = cnt;
    __syncthreads();

    int deg = 0;
#pragma unroll
    for (int i = 0; i < 8; i++) deg += s_cnt[i];

    float acc0 = 0.f, acc1 = 0.f;
    const int c0 = tid, c1 = tid + 256;
    for (int ww = 0; ww < 8; ww++) {
        const int  c   = s_cnt[ww];
        const int* lst = s_idx + ww * seg;
        for (int k = 0; k < c; k++) {
            int j = lst[k];
            const float* nrow = nodes + (size_t)j * d;
            acc0 += nrow[c0];
            acc1 += nrow[c1];
        }
    }
    g_P[(size_t)row * d + c0] = acc0;
    g_P[(size_t)row * d + c1] = acc1;
    if (tid == 0) g_deg[row] = (float)deg;
}

// ---------------------------------------------------------------------------
// Tiled fp32 GEMM: C[M,N] = A[M,K] @ B[K,N], optional epilogue:
//   v = acc * (deg ? 1/deg[row] : 1) + (bias ? bias[col] : 0); relu optional.
// 128x128 block tile, 8x8 per thread, BK=8, 256 threads.
// Requires M%128==0, N%128==0, K%8==0 (holds for 512/4096 shapes).
// ---------------------------------------------------------------------------
__global__ __launch_bounds__(256, 2)
void gemm_kernel(const float* __restrict__ A, const float* __restrict__ B,
                 float* __restrict__ C, int Mdim, int Ndim, int Kdim,
                 const float* __restrict__ bias, const float* __restrict__ deg,
                 int do_relu) {
    __shared__ float sA[8][128];
    __shared__ float sB[8][128];

    const int tid = threadIdx.x;
    const int blockRow = blockIdx.y * 128;
    const int blockCol = blockIdx.x * 128;

    const int tx = tid & 15;   // 0..15  -> column group
    const int ty = tid >> 4;   // 0..15  -> row group

    // A load mapping: m = tid/2 (0..127), kq = (tid&1)*4
    const int am = tid >> 1;
    const int ak = (tid & 1) * 4;
    // B load mapping: k = tid/32 (0..7), nq = (tid&31)*4
    const int bk = tid >> 5;
    const int bn = (tid & 31) * 4;

    float acc[8][8];
#pragma unroll
    for (int i = 0; i < 8; i++)
#pragma unroll
        for (int j = 0; j < 8; j++) acc[i][j] = 0.f;

    const int nTiles = Kdim >> 3;
    for (int kt = 0; kt < nTiles; kt++) {
        const int k0 = kt << 3;
        // load A tile (transposed into smem)
        float4 av = *(const float4*)(A + (size_t)(blockRow + am) * Kdim + k0 + ak);
        sA[ak + 0][am] = av.x;
        sA[ak + 1][am] = av.y;
        sA[ak + 2][am] = av.z;
        sA[ak + 3][am] = av.w;
        // load B tile
        float4 bv = *(const float4*)(B + (size_t)(k0 + bk) * Ndim + blockCol + bn);
        *(float4*)&sB[bk][bn] = bv;
        __syncthreads();

#pragma unroll
        for (int kk = 0; kk < 8; kk++) {
            float a[8], b[8];
#pragma unroll
            for (int i = 0; i < 8; i++) a[i] = sA[kk][ty * 8 + i];
#pragma unroll
            for (int j = 0; j < 8; j++) b[j] = sB[kk][tx * 8 + j];
#pragma unroll
            for (int i = 0; i < 8; i++)
#pragma unroll
                for (int j = 0; j < 8; j++) acc[i][j] = fmaf(a[i], b[j], acc[i][j]);
        }
        __syncthreads();
    }

    // epilogue
    float rdeg[8];
#pragma unroll
    for (int i = 0; i < 8; i++) {
        int row = blockRow + ty * 8 + i;
        rdeg[i] = deg ? (1.0f / deg[row]) : 1.0f;
    }
#pragma unroll
    for (int i = 0; i < 8; i++) {
        int row = blockRow + ty * 8 + i;
#pragma unroll
        for (int j = 0; j < 8; j++) {
            int col = blockCol + tx * 8 + j;
            float v = acc[i][j] * rdeg[i];
            if (bias) v += bias[col];
            if (do_relu) v = fmaxf(v, 0.f);
            C[(size_t)row * Ndim + col] = v;
        }
    }
}

// ---------------------------------------------------------------------------
// launch
// ---------------------------------------------------------------------------
extern "C" void kernel_launch(void* const* d_in, const int* in_sizes, int n_in,
                              void* d_out, int out_size) {
    const float* nodes = (const float*)d_in[0];
    const float* adj   = (const float*)d_in[1];
    const float* W     = (const float*)d_in[2];
    const float* b     = (const float*)d_in[3];
    const float* K     = (const float*)d_in[4];
    // d_in[5]=A_self, d_in[6]=A_neigh, d_in[7]=num_heads: mathematically unused.

    const int D = in_sizes[3];               // 512
    const int N = in_sizes[0] / D;           // 4096
    const int H = in_sizes[4] / (D * D);     // 4
    float* out = (float*)d_out;

    float *pKbar, *pM, *pc, *pP, *pdeg;
    cudaGetSymbolAddress((void**)&pKbar, g_Kbar);
    cudaGetSymbolAddress((void**)&pM,    g_M);
    cudaGetSymbolAddress((void**)&pc,    g_c);
    cudaGetSymbolAddress((void**)&pP,    g_P);
    cudaGetSymbolAddress((void**)&pdeg,  g_deg);

    const int DD = D * D;

    // 1) Kbar = mean_h K[h]
    kbar_kernel<<<(DD + 255) / 256, 256>>>(K, H, DD);

    // 2) c = b @ Kbar
    cvec_kernel<<<(D + 255) / 256, 256>>>(b, D);

    // 3) M = W @ Kbar   (D x D x D)
    {
        dim3 grid(D / 128, D / 128);
        gemm_kernel<<<grid, 256>>>(W, pKbar, pM, D, D, D, nullptr, nullptr, 0);
    }

    // 4) P = adj @ nodes (sparse, deterministic), deg = rowsum(adj)
    agg_kernel<<<N, 256>>>(adj, nodes, N, D);

    // 5) out = relu( (P @ M) / deg + c )
    {
        dim3 grid(D / 128, N / 128);
        gemm_kernel<<<grid, 256>>>(pP, pM, out, N, D, D, pc, pdeg, 1);
    }
    (void)n_in; (void)out_size;
}

// round 2
// speedup vs baseline: 1.6445x; 1.6445x over previous
#include <cuda_runtime.h>
#include <cuda_bf16.h>
#include <cstdint>

#define MAXN 4096
#define MAXD 512

__device__ float g_Kbar[MAXD * MAXD];
__device__ float g_M[MAXD * MAXD];
__device__ float g_c[MAXD];
__device__ float g_P[MAXN * MAXD];
__device__ float g_deg[MAXN];

// ---------------------------------------------------------------------------
// helpers: tf32 split + m16n8k8 tf32 mma
// ---------------------------------------------------------------------------
__device__ __forceinline__ void split_tf32(float x, float& h, float& l) {
    uint32_t u; asm("cvt.rna.tf32.f32 %0, %1;" : "=r"(u) : "f"(x));
    h = __uint_as_float(u);
    float r = x - h;                       // exact in fp32
    uint32_t v; asm("cvt.rna.tf32.f32 %0, %1;" : "=r"(v) : "f"(r));
    l = __uint_as_float(v);
}

__device__ __forceinline__ void mma8(float* d, const uint32_t* a, const uint32_t* b) {
    asm volatile(
        "mma.sync.aligned.m16n8k8.row.col.f32.tf32.tf32.f32 "
        "{%0,%1,%2,%3},{%4,%5,%6,%7},{%8,%9},{%0,%1,%2,%3};\n"
        : "+f"(d[0]), "+f"(d[1]), "+f"(d[2]), "+f"(d[3])
        : "r"(a[0]), "r"(a[1]), "r"(a[2]), "r"(a[3]), "r"(b[0]), "r"(b[1]));
}

// ---------------------------------------------------------------------------
// Kbar = mean over heads of K[h]
// ---------------------------------------------------------------------------
__global__ void kbar_kernel(const float* __restrict__ K, int H, int DD) {
    int i = blockIdx.x * blockDim.x + threadIdx.x;
    if (i < DD) {
        float s = 0.f;
        for (int h = 0; h < H; h++) s += K[(size_t)h * DD + i];
        g_Kbar[i] = s / (float)H;
    }
}

// ---------------------------------------------------------------------------
// c[f] = sum_d b[d] * Kbar[d*D+f]
// ---------------------------------------------------------------------------
__global__ void cvec_kernel(const float* __restrict__ b, int D) {
    int f = blockIdx.x * blockDim.x + threadIdx.x;
    if (f < D) {
        float s = 0.f;
        for (int d = 0; d < D; d++) s += b[d] * g_Kbar[(size_t)d * D + f];
        g_c[f] = s;
    }
}

// ---------------------------------------------------------------------------
// Sparse aggregation: P[i,:] = sum_{j: adj[i,j]>0.5} nodes[j,:]; deg[i]=count.
// One block/row, 256 thr. float4 adj scan, ballot compaction, float2 gather.
// Deterministic: fixed per-warp segment order, fixed ballot order.
// ---------------------------------------------------------------------------
__global__ void agg_kernel(const float* __restrict__ adj,
                           const float* __restrict__ nodes,
                           int n, int d) {
    __shared__ int s_idx[4096];
    __shared__ int s_cnt[8];
    const int row  = blockIdx.x;
    const int tid  = threadIdx.x;
    const int w    = tid >> 5;
    const int lane = tid & 31;
    const unsigned mlt = (1u << lane) - 1u;

    const float* arow = adj + (size_t)row * n;
    const int base = w * 512;             // warp segment (n==4096 -> 512 cols)

    int cnt = 0;
#pragma unroll
    for (int s = 0; s < 4; s++) {
        int c0 = base + s * 128 + lane * 4;
        float4 v = *(const float4*)(arow + c0);
        unsigned m;
        m = __ballot_sync(0xffffffffu, v.x > 0.5f);
        if (v.x > 0.5f) s_idx[base + cnt + __popc(m & mlt)] = c0;
        cnt += __popc(m);
        m = __ballot_sync(0xffffffffu, v.y > 0.5f);
        if (v.y > 0.5f) s_idx[base + cnt + __popc(m & mlt)] = c0 + 1;
        cnt += __popc(m);
        m = __ballot_sync(0xffffffffu, v.z > 0.5f);
        if (v.z > 0.5f) s_idx[base + cnt + __popc(m & mlt)] = c0 + 2;
        cnt += __popc(m);
        m = __ballot_sync(0xffffffffu, v.w > 0.5f);
        if (v.w > 0.5f) s_idx[base + cnt + __popc(m & mlt)] = c0 + 3;
        cnt += __popc(m);
    }
    if (lane == 0) s_cnt[w] = cnt;
    __syncthreads();

    int deg = 0;
#pragma unroll
    for (int i = 0; i < 8; i++) deg += s_cnt[i];

    // gather: each thread owns one float2 column pair
    const float2* nodes2 = (const float2*)nodes;
    const int dc = d >> 1;                // 256 float2 per row
    float2 acc = make_float2(0.f, 0.f);
    for (int ww = 0; ww < 8; ww++) {
        const int  c   = s_cnt[ww];
        const int* lst = s_idx + ww * 512;
        for (int k = 0; k < c; k++) {
            int j = lst[k];
            float2 t2 = nodes2[(size_t)j * dc + tid];
            acc.x += t2.x;
            acc.y += t2.y;
        }
    }
    ((float2*)g_P)[(size_t)row * dc + tid] = acc;
    if (tid == 0) g_deg[row] = (float)deg;
}

// ---------------------------------------------------------------------------
// tf32-split tensor-core GEMM: C = A[MxK] @ B[KxN] fp32, epilogue:
//   v = acc * (deg? 1/deg[row]:1) + (bias? bias[col]:0); optional relu.
// Template: BM x BN CTA tile, warp grid WGM x WGN (8 warps, 256 threads), BK=16.
// Requires M%BM==0, N%BN==0, K%16==0.
// ---------------------------------------------------------------------------
template <int BM, int BN, int WGM, int WGN>
__global__ __launch_bounds__(256, 1)
void gemm_tc(const float* __restrict__ A, const float* __restrict__ B,
             float* __restrict__ C, int Mdim, int Ndim, int Kdim,
             const float* __restrict__ bias, const float* __restrict__ deg,
             int do_relu) {
    constexpr int WM = BM / WGM, WN = BN / WGN;
    constexpr int MT = WM / 16, NT = WN / 8;
    constexpr int LA = BM / 64;           // float4 loads per thread (A tile)
    constexpr int LB = BN / 64;           // float4 loads per thread (B tile)
    constexpr int SA = BM + 8, SB = BN + 8;

    __shared__ float sAhi[16][SA], sAlo[16][SA];
    __shared__ float sBhi[16][SB], sBlo[16][SB];

    const int tid = threadIdx.x, wid = tid >> 5, lane = tid & 31;
    const int g = lane >> 2, t = lane & 3;
    const int wm = (wid / WGN) * WM, wn = (wid % WGN) * WN;
    const int blockRow = blockIdx.y * BM, blockCol = blockIdx.x * BN;

    float acc[MT][NT][4];
#pragma unroll
    for (int i = 0; i < MT; i++)
#pragma unroll
        for (int j = 0; j < NT; j++)
#pragma unroll
            for (int k = 0; k < 4; k++) acc[i][j][k] = 0.f;

    const float* Aptr = A + (size_t)blockRow * Kdim;
    const float* Bptr = B + blockCol;

    float4 ra[LA], rb[LB];
    // preload kt = 0
#pragma unroll
    for (int i = 0; i < LA; i++) {
        int id = tid + i * 256; int r = id >> 2, q = id & 3;
        ra[i] = *(const float4*)(Aptr + (size_t)r * Kdim + q * 4);
    }
#pragma unroll
    for (int i = 0; i < LB; i++) {
        int id = tid + i * 256; int k = id / (BN / 4), nq = id % (BN / 4);
        rb[i] = *(const float4*)(Bptr + (size_t)k * Ndim + nq * 4);
    }

    const int nK = Kdim >> 4;
    for (int kt = 0; kt < nK; kt++) {
        // split + store staged regs to smem
#pragma unroll
        for (int i = 0; i < LA; i++) {
            int id = tid + i * 256; int r = id >> 2, q = id & 3;
            float v[4] = {ra[i].x, ra[i].y, ra[i].z, ra[i].w};
#pragma unroll
            for (int j = 0; j < 4; j++) {
                float h, l; split_tf32(v[j], h, l);
                sAhi[q * 4 + j][r] = h; sAlo[q * 4 + j][r] = l;
            }
        }
#pragma unroll
        for (int i = 0; i < LB; i++) {
            int id = tid + i * 256; int k = id / (BN / 4), nq = id % (BN / 4);
            float v[4] = {rb[i].x, rb[i].y, rb[i].z, rb[i].w};
#pragma unroll
            for (int j = 0; j < 4; j++) {
                float h, l; split_tf32(v[j], h, l);
                sBhi[k][nq * 4 + j] = h; sBlo[k][nq * 4 + j] = l;
            }
        }
        __syncthreads();

        // issue next tile's GMEM loads (overlap with compute below)
        if (kt + 1 < nK) {
            const int k0 = (kt + 1) * 16;
#pragma unroll
            for (int i = 0; i < LA; i++) {
                int id = tid + i * 256; int r = id >> 2, q = id & 3;
                ra[i] = *(const float4*)(Aptr + (size_t)r * Kdim + k0 + q * 4);
            }
#pragma unroll
            for (int i = 0; i < LB; i++) {
                int id = tid + i * 256; int k = id / (BN / 4), nq = id % (BN / 4);
                rb[i] = *(const float4*)(Bptr + (size_t)(k0 + k) * Ndim + nq * 4);
            }
        }

#pragma unroll
        for (int ks = 0; ks < 2; ks++) {
            const int kb = ks * 8;
            uint32_t ah[MT][4], al[MT][4], bh[NT][2], bl[NT][2];
#pragma unroll
            for (int mt = 0; mt < MT; mt++) {
                int r0 = wm + mt * 16 + g;
                ah[mt][0] = __float_as_uint(sAhi[kb + t][r0]);
                ah[mt][1] = __float_as_uint(sAhi[kb + t][r0 + 8]);
                ah[mt][2] = __float_as_uint(sAhi[kb + t + 4][r0]);
                ah[mt][3] = __float_as_uint(sAhi[kb + t + 4][r0 + 8]);
                al[mt][0] = __float_as_uint(sAlo[kb + t][r0]);
                al[mt][1] = __float_as_uint(sAlo[kb + t][r0 + 8]);
                al[mt][2] = __float_as_uint(sAlo[kb + t + 4][r0]);
                al[mt][3] = __float_as_uint(sAlo[kb + t + 4][r0 + 8]);
            }
#pragma unroll
            for (int nt = 0; nt < NT; nt++) {
                int n0 = wn + nt * 8 + g;
                bh[nt][0] = __float_as_uint(sBhi[kb + t][n0]);
                bh[nt][1] = __float_as_uint(sBhi[kb + t + 4][n0]);
                bl[nt][0] = __float_as_uint(sBlo[kb + t][n0]);
                bl[nt][1] = __float_as_uint(sBlo[kb + t + 4][n0]);
            }
#pragma unroll
            for (int mt = 0; mt < MT; mt++)
#pragma unroll
                for (int nt = 0; nt < NT; nt++) {
                    mma8(acc[mt][nt], ah[mt], bh[nt]);
                    mma8(acc[mt][nt], ah[mt], bl[nt]);
                    mma8(acc[mt][nt], al[mt], bh[nt]);
                }
        }
        __syncthreads();
    }

    // epilogue
#pragma unroll
    for (int mt = 0; mt < MT; mt++) {
        int r0 = blockRow + wm + mt * 16 + g;
        float inv0 = deg ? (1.0f / deg[r0])     : 1.0f;
        float inv1 = deg ? (1.0f / deg[r0 + 8]) : 1.0f;
#pragma unroll
        for (int nt = 0; nt < NT; nt++) {
            int c0 = blockCol + wn + nt * 8 + 2 * t;
            float b0 = bias ? bias[c0]     : 0.f;
            float b1 = bias ? bias[c0 + 1] : 0.f;
            float v00 = acc[mt][nt][0] * inv0 + b0;
            float v01 = acc[mt][nt][1] * inv0 + b1;
            float v10 = acc[mt][nt][2] * inv1 + b0;
            float v11 = acc[mt][nt][3] * inv1 + b1;
            if (do_relu) {
                v00 = fmaxf(v00, 0.f); v01 = fmaxf(v01, 0.f);
                v10 = fmaxf(v10, 0.f); v11 = fmaxf(v11, 0.f);
            }
            *(float2*)(C + (size_t)r0 * Ndim + c0)       = make_float2(v00, v01);
            *(float2*)(C + (size_t)(r0 + 8) * Ndim + c0) = make_float2(v10, v11);
        }
    }
}

// ---------------------------------------------------------------------------
// launch
// ---------------------------------------------------------------------------
extern "C" void kernel_launch(void* const* d_in, const int* in_sizes, int n_in,
                              void* d_out, int out_size) {
    const float* nodes = (const float*)d_in[0];
    const float* adj   = (const float*)d_in[1];
    const float* W     = (const float*)d_in[2];
    const float* b     = (const float*)d_in[3];
    const float* K     = (const float*)d_in[4];
    // d_in[5]=A_self, d_in[6]=A_neigh, d_in[7]=num_heads: mathematically unused
    // (softmax of row-constant score + mask == adj/deg exactly).

    const int D = in_sizes[3];               // 512
    const int N = in_sizes[0] / D;           // 4096
    const int H = in_sizes[4] / (D * D);     // 4
    float* out = (float*)d_out;

    float *pKbar, *pM, *pc, *pP, *pdeg;
    cudaGetSymbolAddress((void**)&pKbar, g_Kbar);
    cudaGetSymbolAddress((void**)&pM,    g_M);
    cudaGetSymbolAddress((void**)&pc,    g_c);
    cudaGetSymbolAddress((void**)&pP,    g_P);
    cudaGetSymbolAddress((void**)&pdeg,  g_deg);

    const int DD = D * D;

    // 1) Kbar = mean_h K[h]
    kbar_kernel<<<(DD + 255) / 256, 256>>>(K, H, DD);

    // 2) c = b @ Kbar
    cvec_kernel<<<(D + 255) / 256, 256>>>(b, D);

    // 3) M = W @ Kbar  (512^3, 64x64 tiles -> 64 CTAs)
    {
        dim3 grid(D / 64, D / 64);
        gemm_tc<64, 64, 2, 4><<<grid, 256>>>(W, pKbar, pM, D, D, D,
                                             nullptr, nullptr, 0);
    }

    // 4) P = adj @ nodes (sparse, deterministic), deg = rowsum(adj)
    agg_kernel<<<N, 256>>>(adj, nodes, N, D);

    // 5) out = relu( (P @ M) / deg + c )  (4096x512x512, 128x128 tiles)
    {
        dim3 grid(D / 128, N / 128);
        gemm_tc<128, 128, 4, 2><<<grid, 256>>>(pP, pM, out, N, D, D,
                                               pc, pdeg, 1);
    }
    (void)n_in; (void)out_size;
}